// round 1
// baseline (speedup 1.0000x reference)
#include <cuda_runtime.h>
#include <math.h>

// ---------------- problem constants ----------------
#define Bq_ 4
#define Sq_ 1024
#define Vq_ 50257
#define Dq_ 768
#define Hq_ 3072
#define NHq_ 12
#define DHq_ 64
#define Lq_ 12
#define Mq_ (Bq_*Sq_)   // 4096 rows

// ---------------- scratch (device globals; no allocs allowed) ----------------
__device__ float g_h[Mq_*Dq_];
__device__ float g_a[Mq_*Dq_];
__device__ float g_q[Mq_*Dq_];
__device__ float g_k[Mq_*Dq_];
__device__ float g_v[Mq_*Dq_];
__device__ float g_o[Mq_*Dq_];
__device__ float g_f[Mq_*Hq_];

// ---------------- embedding ----------------
__global__ void embed_kernel(const int* __restrict__ x,
                             const float* __restrict__ tok,
                             const float* __restrict__ pos,
                             float* __restrict__ h) {
    int row = blockIdx.x;            // 0..4095  (= b*S + s)
    int s = row & (Sq_ - 1);
    int tid = x[row];
    const float* tp = tok + (long)tid * Dq_;
    const float* pp = pos + (long)s * Dq_;
    float* hp = h + (long)row * Dq_;
    for (int d = threadIdx.x; d < Dq_; d += 256)
        hp[d] = tp[d] + pp[d];
}

// ---------------- layernorm (one block per row, 256 thr, 3 elems/thr) ----------------
__global__ void ln_kernel(const float* __restrict__ X,
                          const float* __restrict__ w,
                          const float* __restrict__ bb,
                          float* __restrict__ Y) {
    int row = blockIdx.x;
    const float* x = X + (long)row * Dq_;
    float* y = Y + (long)row * Dq_;
    int t = threadIdx.x;
    float v0 = x[t], v1 = x[t + 256], v2 = x[t + 512];

    __shared__ float red[8];
    __shared__ float mean_s, inv_s;

    float s = v0 + v1 + v2;
    #pragma unroll
    for (int o = 16; o > 0; o >>= 1) s += __shfl_down_sync(0xffffffffu, s, o);
    if ((t & 31) == 0) red[t >> 5] = s;
    __syncthreads();
    if (t == 0) {
        float tot = 0.f;
        #pragma unroll
        for (int i = 0; i < 8; i++) tot += red[i];
        mean_s = tot * (1.0f / Dq_);
    }
    __syncthreads();
    float mean = mean_s;
    float d0 = v0 - mean, d1 = v1 - mean, d2 = v2 - mean;
    float q = d0 * d0 + d1 * d1 + d2 * d2;
    #pragma unroll
    for (int o = 16; o > 0; o >>= 1) q += __shfl_down_sync(0xffffffffu, q, o);
    if ((t & 31) == 0) red[t >> 5] = q;
    __syncthreads();
    if (t == 0) {
        float tot = 0.f;
        #pragma unroll
        for (int i = 0; i < 8; i++) tot += red[i];
        inv_s = rsqrtf(tot * (1.0f / Dq_) + 1e-5f);
    }
    __syncthreads();
    float inv = inv_s;
    y[t]       = d0 * inv * w[t]       + bb[t];
    y[t + 256] = d1 * inv * w[t + 256] + bb[t + 256];
    y[t + 512] = d2 * inv * w[t + 512] + bb[t + 512];
}

// ---------------- SGEMM: C = A[MxK] * B[KxN] + bias, epilogues ----------------
// EPI: 0 = plain, 1 = exact GELU, 2 = add residual (res == C allowed)
template<int EPI>
__device__ __forceinline__ void sgemm_body(
    const float* __restrict__ A, const float* __restrict__ Bm,
    const float* __restrict__ bias, const float* __restrict__ res,
    float* __restrict__ C, int M, int N, int K)
{
    __shared__ float As[8][128];
    __shared__ float Bs[8][128];

    int tid = threadIdx.x;
    int bm = blockIdx.y * 128;
    int bn = blockIdx.x * 128;
    int tx = tid & 15;
    int ty = tid >> 4;
    int row0 = ty * 8, col0 = tx * 8;

    float acc[8][8];
    #pragma unroll
    for (int i = 0; i < 8; i++)
        #pragma unroll
        for (int j = 0; j < 8; j++) acc[i][j] = 0.f;

    int arow = tid >> 1, acol = (tid & 1) * 4;
    int brow = tid >> 5, bcol = (tid & 31) * 4;

    const float* Ap = A + (long)(bm + arow) * K + acol;
    const float* Bp = Bm + (long)brow * N + bn + bcol;
    const bool nvec = ((N & 3) == 0);

    int nk = K >> 3;
    for (int kt = 0; kt < nk; ++kt) {
        float4 av = *(const float4*)Ap;
        As[acol][arow]     = av.x;
        As[acol + 1][arow] = av.y;
        As[acol + 2][arow] = av.z;
        As[acol + 3][arow] = av.w;

        if (nvec && (bn + bcol + 3 < N)) {
            float4 bvv = *(const float4*)Bp;
            Bs[brow][bcol]     = bvv.x;
            Bs[brow][bcol + 1] = bvv.y;
            Bs[brow][bcol + 2] = bvv.z;
            Bs[brow][bcol + 3] = bvv.w;
        } else {
            #pragma unroll
            for (int l2 = 0; l2 < 4; l2++)
                Bs[brow][bcol + l2] = (bn + bcol + l2 < N) ? Bp[l2] : 0.f;
        }
        __syncthreads();

        #pragma unroll
        for (int kk = 0; kk < 8; ++kk) {
            float4 a0 = *(const float4*)&As[kk][row0];
            float4 a1 = *(const float4*)&As[kk][row0 + 4];
            float4 b0 = *(const float4*)&Bs[kk][col0];
            float4 b1 = *(const float4*)&Bs[kk][col0 + 4];
            float af[8] = {a0.x, a0.y, a0.z, a0.w, a1.x, a1.y, a1.z, a1.w};
            float bf[8] = {b0.x, b0.y, b0.z, b0.w, b1.x, b1.y, b1.z, b1.w};
            #pragma unroll
            for (int i2 = 0; i2 < 8; i2++)
                #pragma unroll
                for (int j2 = 0; j2 < 8; j2++)
                    acc[i2][j2] += af[i2] * bf[j2];
        }
        __syncthreads();
        Ap += 8;
        Bp += (long)8 * N;
    }

    #pragma unroll
    for (int i2 = 0; i2 < 8; i2++) {
        long mrow = bm + row0 + i2;
        #pragma unroll
        for (int j2 = 0; j2 < 8; j2++) {
            int ncol = bn + col0 + j2;
            if (ncol < N) {
                float val = acc[i2][j2] + bias[ncol];
                if (EPI == 1) val = 0.5f * val * (1.f + erff(val * 0.70710678118654752f));
                if (EPI == 2) val += res[mrow * N + ncol];
                C[mrow * N + ncol] = val;
            }
        }
    }
}

template<int EPI>
__global__ __launch_bounds__(256, 2) void sgemm_kernel(
    const float* __restrict__ A, const float* __restrict__ Bm,
    const float* __restrict__ bias, const float* __restrict__ res,
    float* __restrict__ C, int M, int N, int K)
{
    sgemm_body<EPI>(A, Bm, bias, res, C, M, N, K);
}

// fused QKV: same GEMM body, blockIdx.z selects {q,k,v} weights/outputs
__global__ __launch_bounds__(256, 2) void sgemm_qkv_kernel(
    const float* __restrict__ A,
    const float* __restrict__ B0, const float* __restrict__ B1, const float* __restrict__ B2,
    const float* __restrict__ c0, const float* __restrict__ c1, const float* __restrict__ c2,
    float* __restrict__ O0, float* __restrict__ O1, float* __restrict__ O2,
    int M, int N, int K)
{
    int z = blockIdx.z;
    const float* Bm  = (z == 0) ? B0 : (z == 1) ? B1 : B2;
    const float* bia = (z == 0) ? c0 : (z == 1) ? c1 : c2;
    float* C         = (z == 0) ? O0 : (z == 1) ? O1 : O2;
    sgemm_body<0>(A, Bm, bia, nullptr, C, M, N, K);
}

// ---------------- causal flash attention ----------------
// one 64-thread block per (b, head, query-row); online softmax over 64-key tiles
__global__ __launch_bounds__(64) void attn_kernel(
    const float* __restrict__ Q, const float* __restrict__ Kt,
    const float* __restrict__ Vt, float* __restrict__ O)
{
    int qi = blockIdx.x, h = blockIdx.y, b = blockIdx.z;
    int t = threadIdx.x;

    __shared__ float qs[64];
    __shared__ float Ks[64][65];   // [dim][key]
    __shared__ float Vs[64][65];   // [key][dim]
    __shared__ float ps[64];
    __shared__ float red[64];

    const float scale = 0.125f;    // 1/sqrt(64)
    long qoff = (((long)(b * Sq_ + qi)) * NHq_ + h) * DHq_;
    qs[t] = Q[qoff + t];

    float m = -1e30f, l = 0.f, acc = 0.f;
    __syncthreads();

    for (int j0 = 0; j0 <= qi; j0 += 64) {
        int nj = min(64, qi + 1 - j0);
        const float* Kg = Kt + (((long)(b * Sq_ + j0)) * NHq_ + h) * DHq_;
        const float* Vg = Vt + (((long)(b * Sq_ + j0)) * NHq_ + h) * DHq_;
        for (int j = 0; j < nj; ++j) {
            Ks[t][j] = Kg[(long)j * Dq_ + t];   // coalesced 256B per key
            Vs[j][t] = Vg[(long)j * Dq_ + t];
        }
        __syncthreads();

        // scores: thread t owns key j0+t
        float sc = -1e30f;
        if (t < nj) {
            float a2 = 0.f;
            #pragma unroll 16
            for (int d = 0; d < 64; ++d) a2 += qs[d] * Ks[d][t];
            sc = a2 * scale;
        }
        // tile max
        red[t] = sc; __syncthreads();
        #pragma unroll
        for (int off = 32; off >= 1; off >>= 1) {
            if (t < off) red[t] = fmaxf(red[t], red[t + off]);
            __syncthreads();
        }
        float tmax = red[0]; __syncthreads();
        float mnew = fmaxf(m, tmax);

        float p = (t < nj) ? __expf(sc - mnew) : 0.f;
        ps[t] = p;
        red[t] = p; __syncthreads();
        #pragma unroll
        for (int off = 32; off >= 1; off >>= 1) {
            if (t < off) red[t] += red[t + off];
            __syncthreads();
        }
        float tsum = red[0]; __syncthreads();

        float fac = __expf(m - mnew);
        l = l * fac + tsum;
        m = mnew;
        acc *= fac;

        // thread t now owns dim t: acc += sum_j p_j * V[j][t]
        float a3 = 0.f;
        #pragma unroll 16
        for (int j = 0; j < nj; ++j) a3 += ps[j] * Vs[j][t];
        acc += a3;
        __syncthreads();
    }
    O[qoff + t] = acc / l;
}

// ---------------- launcher ----------------
extern "C" void kernel_launch(void* const* d_in, const int* in_sizes, int n_in,
                              void* d_out, int out_size) {
    const int*   x    = (const int*)  d_in[0];
    const float* tok  = (const float*)d_in[1];
    const float* pos  = (const float*)d_in[2];
    const float* Wq   = (const float*)d_in[3];
    const float* bq   = (const float*)d_in[4];
    const float* Wk   = (const float*)d_in[5];
    const float* bk   = (const float*)d_in[6];
    const float* Wv   = (const float*)d_in[7];
    const float* bv   = (const float*)d_in[8];
    const float* Wo   = (const float*)d_in[9];
    const float* bo   = (const float*)d_in[10];
    const float* ln1w = (const float*)d_in[11];
    const float* ln1b = (const float*)d_in[12];
    const float* ln2w = (const float*)d_in[13];
    const float* ln2b = (const float*)d_in[14];
    const float* W1   = (const float*)d_in[15];
    const float* b1   = (const float*)d_in[16];
    const float* W2   = (const float*)d_in[17];
    const float* b2   = (const float*)d_in[18];
    const float* lnfw = (const float*)d_in[19];
    const float* lnfb = (const float*)d_in[20];
    const float* Wout = (const float*)d_in[21];
    const float* bout = (const float*)d_in[22];
    float* out = (float*)d_out;

    float *h, *a, *q, *k, *v, *o, *f;
    cudaGetSymbolAddress((void**)&h, g_h);
    cudaGetSymbolAddress((void**)&a, g_a);
    cudaGetSymbolAddress((void**)&q, g_q);
    cudaGetSymbolAddress((void**)&k, g_k);
    cudaGetSymbolAddress((void**)&v, g_v);
    cudaGetSymbolAddress((void**)&o, g_o);
    cudaGetSymbolAddress((void**)&f, g_f);

    embed_kernel<<<Mq_, 256>>>(x, tok, pos, h);

    dim3 gD((Dq_ + 127) / 128, Mq_ / 128);        // 6 x 32
    dim3 gH((Hq_ + 127) / 128, Mq_ / 128);        // 24 x 32
    dim3 gV((Vq_ + 127) / 128, Mq_ / 128);        // 393 x 32
    dim3 gQKV((Dq_ + 127) / 128, Mq_ / 128, 3);   // 6 x 32 x 3
    dim3 gAtt(Sq_, NHq_, Bq_);

    for (int i = 0; i < Lq_; ++i) {
        ln_kernel<<<Mq_, 256>>>(h, ln1w + i * Dq_, ln1b + i * Dq_, a);
        sgemm_qkv_kernel<<<gQKV, 256>>>(a,
            Wq + (long)i * Dq_ * Dq_, Wk + (long)i * Dq_ * Dq_, Wv + (long)i * Dq_ * Dq_,
            bq + i * Dq_, bk + i * Dq_, bv + i * Dq_,
            q, k, v, Mq_, Dq_, Dq_);
        attn_kernel<<<gAtt, 64>>>(q, k, v, o);
        sgemm_kernel<2><<<gD, 256>>>(o, Wo + (long)i * Dq_ * Dq_, bo + i * Dq_, h, h, Mq_, Dq_, Dq_);
        ln_kernel<<<Mq_, 256>>>(h, ln2w + i * Dq_, ln2b + i * Dq_, a);
        sgemm_kernel<1><<<gH, 256>>>(a, W1 + (long)i * Dq_ * Hq_, b1 + i * Hq_, nullptr, f, Mq_, Hq_, Dq_);
        sgemm_kernel<2><<<gD, 256>>>(f, W2 + (long)i * Hq_ * Dq_, b2 + i * Dq_, h, h, Mq_, Dq_, Hq_);
    }

    ln_kernel<<<Mq_, 256>>>(h, lnfw, lnfb, a);
    sgemm_kernel<0><<<gV, 256>>>(a, Wout, bout, nullptr, out, Mq_, Vq_, Dq_);
}

// round 2
// speedup vs baseline: 1.0043x; 1.0043x over previous
#include <cuda_runtime.h>
#include <math.h>

// ---------------- problem constants ----------------
#define Bq_ 4
#define Sq_ 1024
#define Vq_ 50257
#define Dq_ 768
#define Hq_ 3072
#define NHq_ 12
#define DHq_ 64
#define Lq_ 12
#define Mq_ (Bq_*Sq_)   // 4096 rows

// ---------------- scratch (device globals; no allocs allowed) ----------------
__device__ float g_h[Mq_*Dq_];
__device__ float g_a[Mq_*Dq_];
__device__ float g_q[Mq_*Dq_];
__device__ float g_k[Mq_*Dq_];
__device__ float g_v[Mq_*Dq_];
__device__ float g_o[Mq_*Dq_];
__device__ float g_f[Mq_*Hq_];

// ---------------- embedding ----------------
__global__ void embed_kernel(const int* __restrict__ x,
                             const float* __restrict__ tok,
                             const float* __restrict__ pos,
                             float* __restrict__ h) {
    int row = blockIdx.x;            // 0..4095  (= b*S + s)
    int s = row & (Sq_ - 1);
    int tid = x[row];
    const float* tp = tok + (long)tid * Dq_;
    const float* pp = pos + (long)s * Dq_;
    float* hp = h + (long)row * Dq_;
    for (int d = threadIdx.x; d < Dq_; d += 256)
        hp[d] = tp[d] + pp[d];
}

// ---------------- layernorm (one block per row, 256 thr, 3 elems/thr) ----------------
__global__ void ln_kernel(const float* __restrict__ X,
                          const float* __restrict__ w,
                          const float* __restrict__ bb,
                          float* __restrict__ Y) {
    int row = blockIdx.x;
    const float* x = X + (long)row * Dq_;
    float* y = Y + (long)row * Dq_;
    int t = threadIdx.x;
    float v0 = x[t], v1 = x[t + 256], v2 = x[t + 512];

    __shared__ float red[8];
    __shared__ float mean_s, inv_s;

    float s = v0 + v1 + v2;
    #pragma unroll
    for (int o = 16; o > 0; o >>= 1) s += __shfl_down_sync(0xffffffffu, s, o);
    if ((t & 31) == 0) red[t >> 5] = s;
    __syncthreads();
    if (t == 0) {
        float tot = 0.f;
        #pragma unroll
        for (int i = 0; i < 8; i++) tot += red[i];
        mean_s = tot * (1.0f / Dq_);
    }
    __syncthreads();
    float mean = mean_s;
    float d0 = v0 - mean, d1 = v1 - mean, d2 = v2 - mean;
    float q = d0 * d0 + d1 * d1 + d2 * d2;
    #pragma unroll
    for (int o = 16; o > 0; o >>= 1) q += __shfl_down_sync(0xffffffffu, q, o);
    if ((t & 31) == 0) red[t >> 5] = q;
    __syncthreads();
    if (t == 0) {
        float tot = 0.f;
        #pragma unroll
        for (int i = 0; i < 8; i++) tot += red[i];
        inv_s = rsqrtf(tot * (1.0f / Dq_) + 1e-5f);
    }
    __syncthreads();
    float inv = inv_s;
    y[t]       = d0 * inv * w[t]       + bb[t];
    y[t + 256] = d1 * inv * w[t + 256] + bb[t + 256];
    y[t + 512] = d2 * inv * w[t + 512] + bb[t + 512];
}

// ---------------- SGEMM: C = A[MxK] * B[KxN] + bias, epilogues ----------------
// EPI: 0 = plain, 1 = exact GELU, 2 = add residual (res == C allowed)
template<int EPI>
__device__ __forceinline__ void sgemm_body(
    const float* __restrict__ A, const float* __restrict__ Bm,
    const float* __restrict__ bias, const float* __restrict__ res,
    float* __restrict__ C, int M, int N, int K)
{
    __shared__ float As[8][128];
    __shared__ float Bs[8][128];

    int tid = threadIdx.x;
    int bm = blockIdx.y * 128;
    int bn = blockIdx.x * 128;
    int tx = tid & 15;
    int ty = tid >> 4;
    int row0 = ty * 8, col0 = tx * 8;

    float acc[8][8];
    #pragma unroll
    for (int i = 0; i < 8; i++)
        #pragma unroll
        for (int j = 0; j < 8; j++) acc[i][j] = 0.f;

    int arow = tid >> 1, acol = (tid & 1) * 4;
    int brow = tid >> 5, bcol = (tid & 31) * 4;

    const float* Ap = A + (long)(bm + arow) * K + acol;
    const float* Bp = Bm + (long)brow * N + bn + bcol;
    const bool nvec = ((N & 3) == 0);

    int nk = K >> 3;
    for (int kt = 0; kt < nk; ++kt) {
        float4 av = *(const float4*)Ap;
        As[acol][arow]     = av.x;
        As[acol + 1][arow] = av.y;
        As[acol + 2][arow] = av.z;
        As[acol + 3][arow] = av.w;

        if (nvec && (bn + bcol + 3 < N)) {
            float4 bvv = *(const float4*)Bp;
            Bs[brow][bcol]     = bvv.x;
            Bs[brow][bcol + 1] = bvv.y;
            Bs[brow][bcol + 2] = bvv.z;
            Bs[brow][bcol + 3] = bvv.w;
        } else {
            #pragma unroll
            for (int l2 = 0; l2 < 4; l2++)
                Bs[brow][bcol + l2] = (bn + bcol + l2 < N) ? Bp[l2] : 0.f;
        }
        __syncthreads();

        #pragma unroll
        for (int kk = 0; kk < 8; ++kk) {
            float4 a0 = *(const float4*)&As[kk][row0];
            float4 a1 = *(const float4*)&As[kk][row0 + 4];
            float4 b0 = *(const float4*)&Bs[kk][col0];
            float4 b1 = *(const float4*)&Bs[kk][col0 + 4];
            float af[8] = {a0.x, a0.y, a0.z, a0.w, a1.x, a1.y, a1.z, a1.w};
            float bf[8] = {b0.x, b0.y, b0.z, b0.w, b1.x, b1.y, b1.z, b1.w};
            #pragma unroll
            for (int i2 = 0; i2 < 8; i2++)
                #pragma unroll
                for (int j2 = 0; j2 < 8; j2++)
                    acc[i2][j2] += af[i2] * bf[j2];
        }
        __syncthreads();
        Ap += 8;
        Bp += (long)8 * N;
    }

    #pragma unroll
    for (int i2 = 0; i2 < 8; i2++) {
        long mrow = bm + row0 + i2;
        #pragma unroll
        for (int j2 = 0; j2 < 8; j2++) {
            int ncol = bn + col0 + j2;
            if (ncol < N) {
                float val = acc[i2][j2] + bias[ncol];
                if (EPI == 1) val = 0.5f * val * (1.f + erff(val * 0.70710678118654752f));
                if (EPI == 2) val += res[mrow * N + ncol];
                C[mrow * N + ncol] = val;
            }
        }
    }
}

template<int EPI>
__global__ __launch_bounds__(256, 2) void sgemm_kernel(
    const float* __restrict__ A, const float* __restrict__ Bm,
    const float* __restrict__ bias, const float* __restrict__ res,
    float* __restrict__ C, int M, int N, int K)
{
    sgemm_body<EPI>(A, Bm, bias, res, C, M, N, K);
}

// fused QKV: same GEMM body, blockIdx.z selects {q,k,v} weights/outputs
__global__ __launch_bounds__(256, 2) void sgemm_qkv_kernel(
    const float* __restrict__ A,
    const float* __restrict__ B0, const float* __restrict__ B1, const float* __restrict__ B2,
    const float* __restrict__ c0, const float* __restrict__ c1, const float* __restrict__ c2,
    float* __restrict__ O0, float* __restrict__ O1, float* __restrict__ O2,
    int M, int N, int K)
{
    int z = blockIdx.z;
    const float* Bm  = (z == 0) ? B0 : (z == 1) ? B1 : B2;
    const float* bia = (z == 0) ? c0 : (z == 1) ? c1 : c2;
    float* C         = (z == 0) ? O0 : (z == 1) ? O1 : O2;
    sgemm_body<0>(A, Bm, bia, nullptr, C, M, N, K);
}

// ---------------- causal flash attention ----------------
// one 64-thread block per (b, head, query-row); online softmax over 64-key tiles
__global__ __launch_bounds__(64) void attn_kernel(
    const float* __restrict__ Q, const float* __restrict__ Kt,
    const float* __restrict__ Vt, float* __restrict__ O)
{
    int qi = blockIdx.x, h = blockIdx.y, b = blockIdx.z;
    int t = threadIdx.x;

    __shared__ float qs[64];
    __shared__ float Ks[64][65];   // [dim][key]
    __shared__ float Vs[64][65];   // [key][dim]
    __shared__ float ps[64];
    __shared__ float red[64];

    const float scale = 0.125f;    // 1/sqrt(64)
    long qoff = (((long)(b * Sq_ + qi)) * NHq_ + h) * DHq_;
    qs[t] = Q[qoff + t];

    float m = -1e30f, l = 0.f, acc = 0.f;
    __syncthreads();

    for (int j0 = 0; j0 <= qi; j0 += 64) {
        int nj = min(64, qi + 1 - j0);
        const float* Kg = Kt + (((long)(b * Sq_ + j0)) * NHq_ + h) * DHq_;
        const float* Vg = Vt + (((long)(b * Sq_ + j0)) * NHq_ + h) * DHq_;
        for (int j = 0; j < nj; ++j) {
            Ks[t][j] = Kg[(long)j * Dq_ + t];   // coalesced 256B per key
            Vs[j][t] = Vg[(long)j * Dq_ + t];
        }
        __syncthreads();

        // scores: thread t owns key j0+t
        float sc = -1e30f;
        if (t < nj) {
            float a2 = 0.f;
            #pragma unroll 16
            for (int d = 0; d < 64; ++d) a2 += qs[d] * Ks[d][t];
            sc = a2 * scale;
        }
        // tile max
        red[t] = sc; __syncthreads();
        #pragma unroll
        for (int off = 32; off >= 1; off >>= 1) {
            if (t < off) red[t] = fmaxf(red[t], red[t + off]);
            __syncthreads();
        }
        float tmax = red[0]; __syncthreads();
        float mnew = fmaxf(m, tmax);

        float p = (t < nj) ? __expf(sc - mnew) : 0.f;
        ps[t] = p;
        red[t] = p; __syncthreads();
        #pragma unroll
        for (int off = 32; off >= 1; off >>= 1) {
            if (t < off) red[t] += red[t + off];
            __syncthreads();
        }
        float tsum = red[0]; __syncthreads();

        float fac = __expf(m - mnew);
        l = l * fac + tsum;
        m = mnew;
        acc *= fac;

        // thread t now owns dim t: acc += sum_j p_j * V[j][t]
        float a3 = 0.f;
        #pragma unroll 16
        for (int j = 0; j < nj; ++j) a3 += ps[j] * Vs[j][t];
        acc += a3;
        __syncthreads();
    }
    O[qoff + t] = acc / l;
}

// ---------------- launcher ----------------
extern "C" void kernel_launch(void* const* d_in, const int* in_sizes, int n_in,
                              void* d_out, int out_size) {
    const int*   x    = (const int*)  d_in[0];
    const float* tok  = (const float*)d_in[1];
    const float* pos  = (const float*)d_in[2];
    const float* Wq   = (const float*)d_in[3];
    const float* bq   = (const float*)d_in[4];
    const float* Wk   = (const float*)d_in[5];
    const float* bk   = (const float*)d_in[6];
    const float* Wv   = (const float*)d_in[7];
    const float* bv   = (const float*)d_in[8];
    const float* Wo   = (const float*)d_in[9];
    const float* bo   = (const float*)d_in[10];
    const float* ln1w = (const float*)d_in[11];
    const float* ln1b = (const float*)d_in[12];
    const float* ln2w = (const float*)d_in[13];
    const float* ln2b = (const float*)d_in[14];
    const float* W1   = (const float*)d_in[15];
    const float* b1   = (const float*)d_in[16];
    const float* W2   = (const float*)d_in[17];
    const float* b2   = (const float*)d_in[18];
    const float* lnfw = (const float*)d_in[19];
    const float* lnfb = (const float*)d_in[20];
    const float* Wout = (const float*)d_in[21];
    const float* bout = (const float*)d_in[22];
    float* out = (float*)d_out;

    float *h, *a, *q, *k, *v, *o, *f;
    cudaGetSymbolAddress((void**)&h, g_h);
    cudaGetSymbolAddress((void**)&a, g_a);
    cudaGetSymbolAddress((void**)&q, g_q);
    cudaGetSymbolAddress((void**)&k, g_k);
    cudaGetSymbolAddress((void**)&v, g_v);
    cudaGetSymbolAddress((void**)&o, g_o);
    cudaGetSymbolAddress((void**)&f, g_f);

    embed_kernel<<<Mq_, 256>>>(x, tok, pos, h);

    dim3 gD((Dq_ + 127) / 128, Mq_ / 128);        // 6 x 32
    dim3 gH((Hq_ + 127) / 128, Mq_ / 128);        // 24 x 32
    dim3 gV((Vq_ + 127) / 128, Mq_ / 128);        // 393 x 32
    dim3 gQKV((Dq_ + 127) / 128, Mq_ / 128, 3);   // 6 x 32 x 3
    dim3 gAtt(Sq_, NHq_, Bq_);

    for (int i = 0; i < Lq_; ++i) {
        ln_kernel<<<Mq_, 256>>>(h, ln1w + i * Dq_, ln1b + i * Dq_, a);
        sgemm_qkv_kernel<<<gQKV, 256>>>(a,
            Wq + (long)i * Dq_ * Dq_, Wk + (long)i * Dq_ * Dq_, Wv + (long)i * Dq_ * Dq_,
            bq + i * Dq_, bk + i * Dq_, bv + i * Dq_,
            q, k, v, Mq_, Dq_, Dq_);
        attn_kernel<<<gAtt, 64>>>(q, k, v, o);
        sgemm_kernel<2><<<gD, 256>>>(o, Wo + (long)i * Dq_ * Dq_, bo + i * Dq_, h, h, Mq_, Dq_, Dq_);
        ln_kernel<<<Mq_, 256>>>(h, ln2w + i * Dq_, ln2b + i * Dq_, a);
        sgemm_kernel<1><<<gH, 256>>>(a, W1 + (long)i * Dq_ * Hq_, b1 + i * Hq_, nullptr, f, Mq_, Hq_, Dq_);
        sgemm_kernel<2><<<gD, 256>>>(f, W2 + (long)i * Hq_ * Dq_, b2 + i * Dq_, h, h, Mq_, Dq_, Hq_);
    }

    ln_kernel<<<Mq_, 256>>>(h, lnfw, lnfb, a);
    sgemm_kernel<0><<<gV, 256>>>(a, Wout, bout, nullptr, out, Mq_, Vq_, Dq_);
}

// round 3
// speedup vs baseline: 2.8714x; 2.8591x over previous
#include <cuda_runtime.h>
#include <cuda_bf16.h>
#include <math.h>
#include <stdint.h>

// ---------------- problem constants ----------------
#define Bq_ 4
#define Sq_ 1024
#define Vq_ 50257
#define VPAD_ 50304
#define Dq_ 768
#define Hq_ 3072
#define NHq_ 12
#define DHq_ 64
#define Lq_ 12
#define Mq_ (Bq_*Sq_)   // 4096 rows

typedef __nv_bfloat16 bf16;

// per-layer transposed-weight block (bf16 elems): wqT,wkT,wvT,woT (4*768*768) + w1T + w2T (2*768*3072)
#define WSQ (768UL*768UL)
#define WSH (768UL*3072UL)
#define LWBLK (4UL*WSQ + 2UL*WSH)            // 7077888
#define WOUT_OFF (LWBLK*12UL)
#define WTOT (WOUT_OFF + (size_t)VPAD_*Dq_)

// ---------------- scratch (device globals; no allocs allowed) ----------------
__device__ float g_h[Mq_*Dq_];
__device__ float g_q[Mq_*Dq_];
__device__ float g_k[Mq_*Dq_];
__device__ float g_v[Mq_*Dq_];
__device__ bf16 g_ahi[Mq_*Dq_], g_alo[Mq_*Dq_];
__device__ bf16 g_ohi[Mq_*Dq_], g_olo[Mq_*Dq_];
__device__ bf16 g_fhi[Mq_*Hq_], g_flo[Mq_*Hq_];
__device__ bf16 g_whi[WTOT], g_wlo[WTOT];

// ---------------- helpers ----------------
__device__ __forceinline__ uint32_t s2u(const void* p) {
    return (uint32_t)__cvta_generic_to_shared(p);
}
__device__ __forceinline__ void cp16(uint32_t d, const void* s) {
    asm volatile("cp.async.cg.shared.global [%0], [%1], 16;\n" :: "r"(d), "l"(s) : "memory");
}
#define CP_COMMIT asm volatile("cp.async.commit_group;\n" ::: "memory")
#define CP_WAIT1  asm volatile("cp.async.wait_group 1;\n" ::: "memory")
#define CP_WAIT0  asm volatile("cp.async.wait_group 0;\n" ::: "memory")

__device__ __forceinline__ void ldsm4(uint32_t &r0, uint32_t &r1, uint32_t &r2, uint32_t &r3,
                                      uint32_t addr) {
    asm volatile("ldmatrix.sync.aligned.m8n8.x4.shared.b16 {%0,%1,%2,%3}, [%4];\n"
        : "=r"(r0), "=r"(r1), "=r"(r2), "=r"(r3) : "r"(addr));
}
__device__ __forceinline__ void mma_bf16(float* c, uint32_t a0, uint32_t a1, uint32_t a2, uint32_t a3,
                                         uint32_t b0, uint32_t b1) {
    asm volatile("mma.sync.aligned.m16n8k16.row.col.f32.bf16.bf16.f32 "
        "{%0,%1,%2,%3},{%4,%5,%6,%7},{%8,%9},{%0,%1,%2,%3};\n"
        : "+f"(c[0]), "+f"(c[1]), "+f"(c[2]), "+f"(c[3])
        : "r"(a0), "r"(a1), "r"(a2), "r"(a3), "r"(b0), "r"(b1));
}
__device__ __forceinline__ void split2(float x, bf16& h, bf16& l) {
    h = __float2bfloat16(x);
    l = __float2bfloat16(x - __bfloat162float(h));
}

// ---------------- weight transpose + split: W[K][Nsrc] -> out[n][k], n < N ----------------
__global__ void tsplit_kernel(const float* __restrict__ W, bf16* __restrict__ hi,
                              bf16* __restrict__ lo, int K, int N, int Nsrc) {
    __shared__ float tile[32][33];
    int k0 = blockIdx.y * 32, n0 = blockIdx.x * 32;
    int tx = threadIdx.x, ty = threadIdx.y;   // 32 x 8
    #pragma unroll
    for (int i = 0; i < 4; i++) {
        int k = k0 + ty + i * 8, n = n0 + tx;
        tile[ty + i * 8][tx] = (n < Nsrc) ? W[(long)k * Nsrc + n] : 0.f;
    }
    __syncthreads();
    #pragma unroll
    for (int i = 0; i < 4; i++) {
        int n = n0 + ty + i * 8, k = k0 + tx;
        float v = tile[tx][ty + i * 8];
        bf16 h, l; split2(v, h, l);
        hi[(long)n * K + k] = h;
        lo[(long)n * K + k] = l;
    }
}

// ---------------- embedding ----------------
__global__ void embed_kernel(const int* __restrict__ x,
                             const float* __restrict__ tok,
                             const float* __restrict__ pos,
                             float* __restrict__ h) {
    int row = blockIdx.x;
    int s = row & (Sq_ - 1);
    int tid = x[row];
    const float* tp = tok + (long)tid * Dq_;
    const float* pp = pos + (long)s * Dq_;
    float* hp = h + (long)row * Dq_;
    for (int d = threadIdx.x; d < Dq_; d += 256)
        hp[d] = tp[d] + pp[d];
}

// ---------------- layernorm -> bf16 hi/lo split output ----------------
__global__ void ln_kernel(const float* __restrict__ X,
                          const float* __restrict__ w,
                          const float* __restrict__ bb,
                          bf16* __restrict__ Yhi, bf16* __restrict__ Ylo) {
    int row = blockIdx.x;
    const float* x = X + (long)row * Dq_;
    int t = threadIdx.x;
    float v0 = x[t], v1 = x[t + 256], v2 = x[t + 512];

    __shared__ float red[8];
    __shared__ float mean_s, inv_s;

    float s = v0 + v1 + v2;
    #pragma unroll
    for (int o = 16; o > 0; o >>= 1) s += __shfl_down_sync(0xffffffffu, s, o);
    if ((t & 31) == 0) red[t >> 5] = s;
    __syncthreads();
    if (t == 0) {
        float tot = 0.f;
        #pragma unroll
        for (int i = 0; i < 8; i++) tot += red[i];
        mean_s = tot * (1.0f / Dq_);
    }
    __syncthreads();
    float mean = mean_s;
    float d0 = v0 - mean, d1 = v1 - mean, d2 = v2 - mean;
    float q = d0 * d0 + d1 * d1 + d2 * d2;
    #pragma unroll
    for (int o = 16; o > 0; o >>= 1) q += __shfl_down_sync(0xffffffffu, q, o);
    if ((t & 31) == 0) red[t >> 5] = q;
    __syncthreads();
    if (t == 0) {
        float tot = 0.f;
        #pragma unroll
        for (int i = 0; i < 8; i++) tot += red[i];
        inv_s = rsqrtf(tot * (1.0f / Dq_) + 1e-5f);
    }
    __syncthreads();
    float inv = inv_s;
    long base = (long)row * Dq_;
    #pragma unroll
    for (int i = 0; i < 3; i++) {
        int c = t + i * 256;
        float dd = (i == 0 ? d0 : i == 1 ? d1 : d2);
        float y = dd * inv * w[c] + bb[c];
        bf16 h, l; split2(y, h, l);
        Yhi[base + c] = h;
        Ylo[base + c] = l;
    }
}

// ---------------- bf16x3 tensor-core GEMM ----------------
// C = A[MxK] * B^T (B stored transposed [N][K] as hi/lo bf16) + bias
// EPI: 0 = fp32 C;  1 = GELU -> split bf16 (Chi,Clo);  2 = fp32 residual add in-place (C)
template<int EPI>
__device__ __forceinline__ void gemm_body(
    const bf16* __restrict__ Ahi, const bf16* __restrict__ Alo,
    const bf16* __restrict__ Bhi, const bf16* __restrict__ Blo,
    const float* __restrict__ bias,
    float* __restrict__ C, bf16* __restrict__ Chi, bf16* __restrict__ Clo,
    int K, int N, int Nout)
{
    extern __shared__ bf16 sm[];   // [2 buf][4 arr][128][40]
    uint32_t smb = s2u(sm);
    int tid = threadIdx.x;
    int bm = blockIdx.y * 128, bn = blockIdx.x * 128;
    int warp = tid >> 5, lane = tid & 31;
    int wm = warp >> 2, wn = warp & 3;   // 2 x 4 warps -> 64 x 32 warp tile

    float acc[4][4][4];
    #pragma unroll
    for (int i = 0; i < 4; i++)
        #pragma unroll
        for (int j = 0; j < 4; j++)
            #pragma unroll
            for (int k = 0; k < 4; k++) acc[i][j][k] = 0.f;

    const bf16* srcs[4] = { Ahi + (long)bm * K, Alo + (long)bm * K,
                            Bhi + (long)bn * K, Blo + (long)bn * K };

    int nk = K >> 5;

    // stage a k-tile into buffer b
    auto issue = [&](int b, int kt) {
        int k0 = kt * 32;
        #pragma unroll
        for (int arr = 0; arr < 4; arr++) {
            #pragma unroll
            for (int i = 0; i < 2; i++) {
                int ch = tid + i * 256;          // 0..511
                int row = ch >> 2, cg = ch & 3;  // 128 rows x 4 chunks of 8 halves
                uint32_t dst = smb + ((((b * 4 + arr) * 128 + row) * 40) + cg * 8) * 2;
                cp16(dst, srcs[arr] + (long)row * K + k0 + cg * 8);
            }
        }
    };

    issue(0, 0); CP_COMMIT;

    for (int kt = 0; kt < nk; ++kt) {
        int cur = kt & 1;
        if (kt + 1 < nk) { issue(cur ^ 1, kt + 1); CP_COMMIT; CP_WAIT1; }
        else            { CP_WAIT0; }
        __syncthreads();

        #pragma unroll
        for (int ks = 0; ks < 2; ++ks) {
            int lrow = lane & 15, lcg = lane >> 4;
            uint32_t ah[4][4], al[4][4];
            #pragma unroll
            for (int mf = 0; mf < 4; mf++) {
                int row = wm * 64 + mf * 16 + lrow;
                int col = ks * 16 + lcg * 8;
                uint32_t a0 = smb + ((((cur * 4 + 0) * 128 + row) * 40) + col) * 2;
                uint32_t a1 = smb + ((((cur * 4 + 1) * 128 + row) * 40) + col) * 2;
                ldsm4(ah[mf][0], ah[mf][1], ah[mf][2], ah[mf][3], a0);
                ldsm4(al[mf][0], al[mf][1], al[mf][2], al[mf][3], a1);
            }
            uint32_t bh[2][4], bl[2][4];
            #pragma unroll
            for (int nf2 = 0; nf2 < 2; nf2++) {
                int row = wn * 32 + nf2 * 16 + lrow;
                int col = ks * 16 + lcg * 8;
                uint32_t b0 = smb + ((((cur * 4 + 2) * 128 + row) * 40) + col) * 2;
                uint32_t b1 = smb + ((((cur * 4 + 3) * 128 + row) * 40) + col) * 2;
                ldsm4(bh[nf2][0], bh[nf2][1], bh[nf2][2], bh[nf2][3], b0);
                ldsm4(bl[nf2][0], bl[nf2][1], bl[nf2][2], bl[nf2][3], b1);
            }
            #pragma unroll
            for (int mf = 0; mf < 4; mf++) {
                #pragma unroll
                for (int nf = 0; nf < 4; nf++) {
                    int g = nf >> 1, o = nf & 1;
                    uint32_t b0h = bh[g][o], b1h = bh[g][o + 2];
                    uint32_t b0l = bl[g][o], b1l = bl[g][o + 2];
                    float* c = acc[mf][nf];
                    mma_bf16(c, ah[mf][0], ah[mf][1], ah[mf][2], ah[mf][3], b0h, b1h);
                    mma_bf16(c, ah[mf][0], ah[mf][1], ah[mf][2], ah[mf][3], b0l, b1l);
                    mma_bf16(c, al[mf][0], al[mf][1], al[mf][2], al[mf][3], b0h, b1h);
                }
            }
        }
        __syncthreads();
    }

    // epilogue
    int r = lane >> 2, c2 = (lane & 3) * 2;
    #pragma unroll
    for (int mf = 0; mf < 4; mf++) {
        #pragma unroll
        for (int nf = 0; nf < 4; nf++) {
            #pragma unroll
            for (int half = 0; half < 2; half++) {
                long row = bm + wm * 64 + mf * 16 + r + half * 8;
                #pragma unroll
                for (int e = 0; e < 2; e++) {
                    int col = bn + wn * 32 + nf * 8 + c2 + e;
                    if (col < Nout) {
                        float v = acc[mf][nf][half * 2 + e] + bias[col];
                        if (EPI == 1) {
                            v = 0.5f * v * (1.f + erff(v * 0.70710678118654752f));
                            bf16 h, l; split2(v, h, l);
                            Chi[row * N + col] = h;
                            Clo[row * N + col] = l;
                        } else if (EPI == 2) {
                            v += C[row * (long)Nout + col];
                            C[row * (long)Nout + col] = v;
                        } else {
                            C[row * (long)Nout + col] = v;
                        }
                    }
                }
            }
        }
    }
}

template<int EPI>
__global__ __launch_bounds__(256, 1) void gemm_kernel(
    const bf16* __restrict__ Ahi, const bf16* __restrict__ Alo,
    const bf16* __restrict__ Bhi, const bf16* __restrict__ Blo,
    const float* __restrict__ bias,
    float* __restrict__ C, bf16* __restrict__ Chi, bf16* __restrict__ Clo,
    int K, int N, int Nout)
{
    gemm_body<EPI>(Ahi, Alo, Bhi, Blo, bias, C, Chi, Clo, K, N, Nout);
}

// fused QKV: blockIdx.z selects q/k/v weight block + bias + output
__global__ __launch_bounds__(256, 1) void gemm_qkv_kernel(
    const bf16* __restrict__ Ahi, const bf16* __restrict__ Alo,
    const bf16* __restrict__ whi, const bf16* __restrict__ wlo,  // layer base
    const float* __restrict__ bq, const float* __restrict__ bk, const float* __restrict__ bv,
    float* __restrict__ Oq, float* __restrict__ Ok, float* __restrict__ Ov)
{
    int z = blockIdx.z;
    const bf16* Bh = whi + (size_t)z * WSQ;
    const bf16* Bl = wlo + (size_t)z * WSQ;
    const float* bias = (z == 0) ? bq : (z == 1) ? bk : bv;
    float* C = (z == 0) ? Oq : (z == 1) ? Ok : Ov;
    gemm_body<0>(Ahi, Alo, Bh, Bl, bias, C, nullptr, nullptr, Dq_, Dq_, Dq_);
}

// ---------------- causal flash attention: 64q x 64k tiles, 256 threads ----------------
// thread (qg = t>>4, jg = t&15): scores tile 4q x {jg, jg+16, jg+32, jg+48};
// PV tile 4q x 4d (d = jg*4..+3). Output written as bf16 hi/lo split.
__global__ __launch_bounds__(256) void attn_kernel(
    const float* __restrict__ Q, const float* __restrict__ Kg,
    const float* __restrict__ Vg, bf16* __restrict__ Ohi, bf16* __restrict__ Olo)
{
    extern __shared__ float smf[];
    float* Qs = smf;              // 64 x 68
    float* Ks = Qs + 64 * 68;
    float* Vs = Ks + 64 * 68;
    float* Ps = Vs + 64 * 68;

    int t = threadIdx.x;
    int q0 = blockIdx.x * 64, h = blockIdx.y, b = blockIdx.z;
    int qg = t >> 4, jg = t & 15;

    const float* Qp = Q + ((long)(b * Sq_ + q0)) * Dq_ + h * DHq_;
    #pragma unroll
    for (int i = 0; i < 16; i++) {
        int idx = t + i * 256;
        int row = idx >> 6, col = idx & 63;
        Qs[row * 68 + col] = Qp[(long)row * Dq_ + col];
    }

    float m[4], l[4], acc[4][4];
    #pragma unroll
    for (int i = 0; i < 4; i++) {
        m[i] = -1e30f; l[i] = 0.f;
        #pragma unroll
        for (int d = 0; d < 4; d++) acc[i][d] = 0.f;
    }
    __syncthreads();

    const float4* Qs4 = (const float4*)Qs;
    const float4* Ks4 = (const float4*)Ks;
    const float4* Vs4 = (const float4*)Vs;

    for (int j0 = 0; j0 <= q0; j0 += 64) {
        const float* Kp = Kg + ((long)(b * Sq_ + j0)) * Dq_ + h * DHq_;
        const float* Vp = Vg + ((long)(b * Sq_ + j0)) * Dq_ + h * DHq_;
        #pragma unroll
        for (int i = 0; i < 16; i++) {
            int idx = t + i * 256;
            int row = idx >> 6, col = idx & 63;
            Ks[row * 68 + col] = Kp[(long)row * Dq_ + col];
            Vs[row * 68 + col] = Vp[(long)row * Dq_ + col];
        }
        __syncthreads();

        // scores: 4 q-rows x 4 j-cols per thread
        float s[4][4];
        #pragma unroll
        for (int i = 0; i < 4; i++)
            #pragma unroll
            for (int jj = 0; jj < 4; jj++) s[i][jj] = 0.f;

        #pragma unroll
        for (int d4 = 0; d4 < 16; d4++) {
            float4 kv[4], qv[4];
            #pragma unroll
            for (int jj = 0; jj < 4; jj++) kv[jj] = Ks4[(jg + 16 * jj) * 17 + d4];
            #pragma unroll
            for (int i = 0; i < 4; i++) qv[i] = Qs4[(qg * 4 + i) * 17 + d4];
            #pragma unroll
            for (int i = 0; i < 4; i++)
                #pragma unroll
                for (int jj = 0; jj < 4; jj++) {
                    s[i][jj] += qv[i].x * kv[jj].x + qv[i].y * kv[jj].y
                              + qv[i].z * kv[jj].z + qv[i].w * kv[jj].w;
                }
        }

        // mask + row max
        float pmax[4];
        #pragma unroll
        for (int i = 0; i < 4; i++) {
            int qrow = q0 + qg * 4 + i;
            pmax[i] = -1e30f;
            #pragma unroll
            for (int jj = 0; jj < 4; jj++) {
                int j = jg + 16 * jj;
                float v = s[i][jj] * 0.125f;
                if (j0 + j > qrow) v = -1e30f;
                s[i][jj] = v;
                pmax[i] = fmaxf(pmax[i], v);
            }
        }
        #pragma unroll
        for (int o = 1; o < 16; o <<= 1)
            #pragma unroll
            for (int i = 0; i < 4; i++)
                pmax[i] = fmaxf(pmax[i], __shfl_xor_sync(0xffffffffu, pmax[i], o));

        float fac[4], psum[4];
        #pragma unroll
        for (int i = 0; i < 4; i++) {
            float mnew = fmaxf(m[i], pmax[i]);
            fac[i] = __expf(m[i] - mnew);
            m[i] = mnew;
            psum[i] = 0.f;
            #pragma unroll
            for (int jj = 0; jj < 4; jj++) {
                float p = __expf(s[i][jj] - mnew);
                Ps[(qg * 4 + i) * 68 + jg + 16 * jj] = p;
                psum[i] += p;
            }
        }
        #pragma unroll
        for (int o = 1; o < 16; o <<= 1)
            #pragma unroll
            for (int i = 0; i < 4; i++)
                psum[i] += __shfl_xor_sync(0xffffffffu, psum[i], o);
        #pragma unroll
        for (int i = 0; i < 4; i++) {
            l[i] = l[i] * fac[i] + psum[i];
            #pragma unroll
            for (int d = 0; d < 4; d++) acc[i][d] *= fac[i];
        }
        __syncthreads();   // Ps visible to all; also guards Ks/Vs reuse

        // PV: 4 q-rows x 4 d-cols (d = jg*4..+3)
        #pragma unroll 4
        for (int j = 0; j < 64; j++) {
            float4 vv = Vs4[j * 17 + jg];
            #pragma unroll
            for (int i = 0; i < 4; i++) {
                float p = Ps[(qg * 4 + i) * 68 + j];
                acc[i][0] += p * vv.x;
                acc[i][1] += p * vv.y;
                acc[i][2] += p * vv.z;
                acc[i][3] += p * vv.w;
            }
        }
        __syncthreads();
    }

    #pragma unroll
    for (int i = 0; i < 4; i++) {
        float invl = 1.f / l[i];
        long base = (long)(b * Sq_ + q0 + qg * 4 + i) * Dq_ + h * DHq_ + jg * 4;
        #pragma unroll
        for (int d = 0; d < 4; d++) {
            float v = acc[i][d] * invl;
            bf16 hh, ll; split2(v, hh, ll);
            Ohi[base + d] = hh;
            Olo[base + d] = ll;
        }
    }
}

// ---------------- launcher ----------------
extern "C" void kernel_launch(void* const* d_in, const int* in_sizes, int n_in,
                              void* d_out, int out_size) {
    const int*   x    = (const int*)  d_in[0];
    const float* tok  = (const float*)d_in[1];
    const float* pos  = (const float*)d_in[2];
    const float* Wq   = (const float*)d_in[3];
    const float* bq   = (const float*)d_in[4];
    const float* Wk   = (const float*)d_in[5];
    const float* bk   = (const float*)d_in[6];
    const float* Wv   = (const float*)d_in[7];
    const float* bv   = (const float*)d_in[8];
    const float* Wo   = (const float*)d_in[9];
    const float* bo   = (const float*)d_in[10];
    const float* ln1w = (const float*)d_in[11];
    const float* ln1b = (const float*)d_in[12];
    const float* ln2w = (const float*)d_in[13];
    const float* ln2b = (const float*)d_in[14];
    const float* W1   = (const float*)d_in[15];
    const float* b1   = (const float*)d_in[16];
    const float* W2   = (const float*)d_in[17];
    const float* b2   = (const float*)d_in[18];
    const float* lnfw = (const float*)d_in[19];
    const float* lnfb = (const float*)d_in[20];
    const float* Wout = (const float*)d_in[21];
    const float* bout = (const float*)d_in[22];
    float* out = (float*)d_out;

    float *h, *q, *k, *v;
    bf16 *ahi, *alo, *ohi, *olo, *fhi, *flo, *whi, *wlo;
    cudaGetSymbolAddress((void**)&h, g_h);
    cudaGetSymbolAddress((void**)&q, g_q);
    cudaGetSymbolAddress((void**)&k, g_k);
    cudaGetSymbolAddress((void**)&v, g_v);
    cudaGetSymbolAddress((void**)&ahi, g_ahi);
    cudaGetSymbolAddress((void**)&alo, g_alo);
    cudaGetSymbolAddress((void**)&ohi, g_ohi);
    cudaGetSymbolAddress((void**)&olo, g_olo);
    cudaGetSymbolAddress((void**)&fhi, g_fhi);
    cudaGetSymbolAddress((void**)&flo, g_flo);
    cudaGetSymbolAddress((void**)&whi, g_whi);
    cudaGetSymbolAddress((void**)&wlo, g_wlo);

    const int GEMM_SMEM = 2 * 4 * 128 * 40 * 2;       // 81920
    const int ATTN_SMEM = 4 * 64 * 68 * 4;            // 69632
    cudaFuncSetAttribute(gemm_kernel<0>, cudaFuncAttributeMaxDynamicSharedMemorySize, GEMM_SMEM);
    cudaFuncSetAttribute(gemm_kernel<1>, cudaFuncAttributeMaxDynamicSharedMemorySize, GEMM_SMEM);
    cudaFuncSetAttribute(gemm_kernel<2>, cudaFuncAttributeMaxDynamicSharedMemorySize, GEMM_SMEM);
    cudaFuncSetAttribute(gemm_qkv_kernel, cudaFuncAttributeMaxDynamicSharedMemorySize, GEMM_SMEM);
    cudaFuncSetAttribute(attn_kernel, cudaFuncAttributeMaxDynamicSharedMemorySize, ATTN_SMEM);

    // ---- weight prep: transpose + bf16 hi/lo split ----
    dim3 tb(32, 8);
    dim3 gQQ(768 / 32, 768 / 32);
    dim3 gDH(Hq_ / 32, 768 / 32);    // W1: K=768 rows, N=3072 out-rows
    dim3 gHD(768 / 32, Hq_ / 32);    // W2: K=3072 rows, N=768 out-rows
    dim3 gOut(VPAD_ / 32, 768 / 32);
    for (int i = 0; i < Lq_; ++i) {
        size_t off = (size_t)i * LWBLK;
        tsplit_kernel<<<gQQ, tb>>>(Wq + (long)i * WSQ, whi + off,            wlo + off,            768, 768, 768);
        tsplit_kernel<<<gQQ, tb>>>(Wk + (long)i * WSQ, whi + off + WSQ,      wlo + off + WSQ,      768, 768, 768);
        tsplit_kernel<<<gQQ, tb>>>(Wv + (long)i * WSQ, whi + off + 2 * WSQ,  wlo + off + 2 * WSQ,  768, 768, 768);
        tsplit_kernel<<<gQQ, tb>>>(Wo + (long)i * WSQ, whi + off + 3 * WSQ,  wlo + off + 3 * WSQ,  768, 768, 768);
        tsplit_kernel<<<gDH, tb>>>(W1 + (long)i * WSH, whi + off + 4 * WSQ,  wlo + off + 4 * WSQ,  768, Hq_, Hq_);
        tsplit_kernel<<<gHD, tb>>>(W2 + (long)i * WSH, whi + off + 4 * WSQ + WSH, wlo + off + 4 * WSQ + WSH, Hq_, 768, 768);
    }
    tsplit_kernel<<<gOut, tb>>>(Wout, whi + WOUT_OFF, wlo + WOUT_OFF, 768, VPAD_, Vq_);

    embed_kernel<<<Mq_, 256>>>(x, tok, pos, h);

    dim3 gD(Dq_ / 128, Mq_ / 128);          // 6 x 32
    dim3 gH(Hq_ / 128, Mq_ / 128);          // 24 x 32
    dim3 gV(VPAD_ / 128, Mq_ / 128);        // 393 x 32
    dim3 gQKV(Dq_ / 128, Mq_ / 128, 3);     // 6 x 32 x 3
    dim3 gAtt(Sq_ / 64, NHq_, Bq_);         // 16 x 12 x 4

    for (int i = 0; i < Lq_; ++i) {
        size_t off = (size_t)i * LWBLK;
        ln_kernel<<<Mq_, 256>>>(h, ln1w + i * Dq_, ln1b + i * Dq_, ahi, alo);
        gemm_qkv_kernel<<<gQKV, 256, GEMM_SMEM>>>(ahi, alo, whi + off, wlo + off,
            bq + i * Dq_, bk + i * Dq_, bv + i * Dq_, q, k, v);
        attn_kernel<<<gAtt, 256, ATTN_SMEM>>>(q, k, v, ohi, olo);
        gemm_kernel<2><<<gD, 256, GEMM_SMEM>>>(ohi, olo, whi + off + 3 * WSQ, wlo + off + 3 * WSQ,
            bo + i * Dq_, h, nullptr, nullptr, Dq_, Dq_, Dq_);
        ln_kernel<<<Mq_, 256>>>(h, ln2w + i * Dq_, ln2b + i * Dq_, ahi, alo);
        gemm_kernel<1><<<gH, 256, GEMM_SMEM>>>(ahi, alo, whi + off + 4 * WSQ, wlo + off + 4 * WSQ,
            b1 + i * Hq_, nullptr, fhi, flo, Dq_, Hq_, Hq_);
        gemm_kernel<2><<<gD, 256, GEMM_SMEM>>>(fhi, flo, whi + off + 4 * WSQ + WSH, wlo + off + 4 * WSQ + WSH,
            b2 + i * Dq_, h, nullptr, nullptr, Hq_, Dq_, Dq_);
    }

    ln_kernel<<<Mq_, 256>>>(h, lnfw, lnfb, ahi, alo);
    gemm_kernel<0><<<gV, 256, GEMM_SMEM>>>(ahi, alo, whi + WOUT_OFF, wlo + WOUT_OFF,
        bout, out, nullptr, nullptr, Dq_, VPAD_, Vq_);
}

// round 5
// speedup vs baseline: 3.1717x; 1.1046x over previous
#include <cuda_runtime.h>
#include <cuda_bf16.h>
#include <math.h>
#include <stdint.h>

// ---------------- problem constants ----------------
#define Bq_ 4
#define Sq_ 1024
#define Vq_ 50257
#define VPAD_ 50304
#define Dq_ 768
#define Hq_ 3072
#define NHq_ 12
#define DHq_ 64
#define Lq_ 12
#define Mq_ (Bq_*Sq_)   // 4096 rows

typedef __nv_bfloat16 bf16;

#define WSQ (768UL*768UL)
#define WSH (768UL*3072UL)
#define LWBLK (4UL*WSQ + 2UL*WSH)
#define WOUT_OFF (LWBLK*12UL)
#define WTOT (WOUT_OFF + (size_t)VPAD_*Dq_)

// ---------------- scratch (device globals; no allocs allowed) ----------------
__device__ float g_h[Mq_*Dq_];
__device__ bf16 g_ahi[Mq_*Dq_], g_alo[Mq_*Dq_];
__device__ bf16 g_qhi[Mq_*Dq_], g_qlo[Mq_*Dq_];
__device__ bf16 g_khi[Mq_*Dq_], g_klo[Mq_*Dq_];
__device__ bf16 g_vhi[Mq_*Dq_], g_vlo[Mq_*Dq_];
__device__ bf16 g_ohi[Mq_*Dq_], g_olo[Mq_*Dq_];
__device__ bf16 g_fhi[Mq_*Hq_], g_flo[Mq_*Hq_];
__device__ bf16 g_whi[WTOT], g_wlo[WTOT];

// ---------------- helpers ----------------
__device__ __forceinline__ uint32_t s2u(const void* p) {
    return (uint32_t)__cvta_generic_to_shared(p);
}
__device__ __forceinline__ void cp16(uint32_t d, const void* s) {
    asm volatile("cp.async.cg.shared.global [%0], [%1], 16;\n" :: "r"(d), "l"(s) : "memory");
}
#define CP_COMMIT asm volatile("cp.async.commit_group;\n" ::: "memory")
#define CP_WAIT1  asm volatile("cp.async.wait_group 1;\n" ::: "memory")
#define CP_WAIT0  asm volatile("cp.async.wait_group 0;\n" ::: "memory")

__device__ __forceinline__ void ldsm4(uint32_t &r0, uint32_t &r1, uint32_t &r2, uint32_t &r3,
                                      uint32_t addr) {
    asm volatile("ldmatrix.sync.aligned.m8n8.x4.shared.b16 {%0,%1,%2,%3}, [%4];\n"
        : "=r"(r0), "=r"(r1), "=r"(r2), "=r"(r3) : "r"(addr));
}
__device__ __forceinline__ void ldsm4t(uint32_t &r0, uint32_t &r1, uint32_t &r2, uint32_t &r3,
                                       uint32_t addr) {
    asm volatile("ldmatrix.sync.aligned.m8n8.x4.trans.shared.b16 {%0,%1,%2,%3}, [%4];\n"
        : "=r"(r0), "=r"(r1), "=r"(r2), "=r"(r3) : "r"(addr));
}
__device__ __forceinline__ void mma_bf16(float* c, uint32_t a0, uint32_t a1, uint32_t a2, uint32_t a3,
                                         uint32_t b0, uint32_t b1) {
    asm volatile("mma.sync.aligned.m16n8k16.row.col.f32.bf16.bf16.f32 "
        "{%0,%1,%2,%3},{%4,%5,%6,%7},{%8,%9},{%0,%1,%2,%3};\n"
        : "+f"(c[0]), "+f"(c[1]), "+f"(c[2]), "+f"(c[3])
        : "r"(a0), "r"(a1), "r"(a2), "r"(a3), "r"(b0), "r"(b1));
}
__device__ __forceinline__ void split2(float x, bf16& h, bf16& l) {
    h = __float2bfloat16(x);
    l = __float2bfloat16(x - __bfloat162float(h));
}
__device__ __forceinline__ uint32_t packbf2(float a, float b) {
    __nv_bfloat162 t = __floats2bfloat162_rn(a, b);   // .x=a(low), .y=b(high)
    return *(uint32_t*)&t;
}

// ---------------- weight transpose + split (batched variants) ----------------
__device__ __forceinline__ void tsplit_body(const float* __restrict__ W, bf16* __restrict__ hi,
                                            bf16* __restrict__ lo, int K, int Nsrc) {
    __shared__ float tile[32][33];
    int k0 = blockIdx.y * 32, n0 = blockIdx.x * 32;
    int tx = threadIdx.x, ty = threadIdx.y;
    #pragma unroll
    for (int i = 0; i < 4; i++) {
        int k = k0 + ty + i * 8, n = n0 + tx;
        tile[ty + i * 8][tx] = (n < Nsrc) ? W[(long)k * Nsrc + n] : 0.f;
    }
    __syncthreads();
    #pragma unroll
    for (int i = 0; i < 4; i++) {
        int n = n0 + ty + i * 8, k = k0 + tx;
        float v = tile[tx][ty + i * 8];
        bf16 h, l; split2(v, h, l);
        hi[(long)n * K + k] = h;
        lo[(long)n * K + k] = l;
    }
}

__global__ void tsplit_sq_kernel(const float* __restrict__ Wq, const float* __restrict__ Wk,
                                 const float* __restrict__ Wv, const float* __restrict__ Wo,
                                 bf16* __restrict__ hi, bf16* __restrict__ lo) {
    int z = blockIdx.z, layer = z >> 2, which = z & 3;
    const float* W = (which == 0 ? Wq : which == 1 ? Wk : which == 2 ? Wv : Wo) + (size_t)layer * WSQ;
    size_t off = (size_t)layer * LWBLK + (size_t)which * WSQ;
    tsplit_body(W, hi + off, lo + off, 768, 768);
}
__global__ void tsplit_w1_kernel(const float* __restrict__ W1, bf16* __restrict__ hi, bf16* __restrict__ lo) {
    int layer = blockIdx.z;
    size_t off = (size_t)layer * LWBLK + 4 * WSQ;
    tsplit_body(W1 + (size_t)layer * WSH, hi + off, lo + off, 768, Hq_);
}
__global__ void tsplit_w2_kernel(const float* __restrict__ W2, bf16* __restrict__ hi, bf16* __restrict__ lo) {
    int layer = blockIdx.z;
    size_t off = (size_t)layer * LWBLK + 4 * WSQ + WSH;
    tsplit_body(W2 + (size_t)layer * WSH, hi + off, lo + off, Hq_, 768);
}
__global__ void tsplit_out_kernel(const float* __restrict__ W, bf16* __restrict__ hi, bf16* __restrict__ lo) {
    tsplit_body(W, hi + WOUT_OFF, lo + WOUT_OFF, 768, Vq_);
}

// ---------------- embedding ----------------
__global__ void embed_kernel(const int* __restrict__ x,
                             const float* __restrict__ tok,
                             const float* __restrict__ pos,
                             float* __restrict__ h) {
    int row = blockIdx.x;
    int s = row & (Sq_ - 1);
    int tid = x[row];
    const float* tp = tok + (long)tid * Dq_;
    const float* pp = pos + (long)s * Dq_;
    float* hp = h + (long)row * Dq_;
    for (int d = threadIdx.x; d < Dq_; d += 256)
        hp[d] = tp[d] + pp[d];
}

// ---------------- layernorm -> bf16 hi/lo split output ----------------
__global__ void ln_kernel(const float* __restrict__ X,
                          const float* __restrict__ w,
                          const float* __restrict__ bb,
                          bf16* __restrict__ Yhi, bf16* __restrict__ Ylo) {
    int row = blockIdx.x;
    const float* x = X + (long)row * Dq_;
    int t = threadIdx.x;
    float v0 = x[t], v1 = x[t + 256], v2 = x[t + 512];

    __shared__ float red[8];
    __shared__ float mean_s, inv_s;

    float s = v0 + v1 + v2;
    #pragma unroll
    for (int o = 16; o > 0; o >>= 1) s += __shfl_down_sync(0xffffffffu, s, o);
    if ((t & 31) == 0) red[t >> 5] = s;
    __syncthreads();
    if (t == 0) {
        float tot = 0.f;
        #pragma unroll
        for (int i = 0; i < 8; i++) tot += red[i];
        mean_s = tot * (1.0f / Dq_);
    }
    __syncthreads();
    float mean = mean_s;
    float d0 = v0 - mean, d1 = v1 - mean, d2 = v2 - mean;
    float q = d0 * d0 + d1 * d1 + d2 * d2;
    #pragma unroll
    for (int o = 16; o > 0; o >>= 1) q += __shfl_down_sync(0xffffffffu, q, o);
    if ((t & 31) == 0) red[t >> 5] = q;
    __syncthreads();
    if (t == 0) {
        float tot = 0.f;
        #pragma unroll
        for (int i = 0; i < 8; i++) tot += red[i];
        inv_s = rsqrtf(tot * (1.0f / Dq_) + 1e-5f);
    }
    __syncthreads();
    float inv = inv_s;
    long base = (long)row * Dq_;
    #pragma unroll
    for (int i = 0; i < 3; i++) {
        int c = t + i * 256;
        float dd = (i == 0 ? d0 : i == 1 ? d1 : d2);
        float y = dd * inv * w[c] + bb[c];
        bf16 h, l; split2(y, h, l);
        Yhi[base + c] = h;
        Ylo[base + c] = l;
    }
}

// ---------------- bf16x3 HMMA GEMM (proven round-3 body) ----------------
// C = A[MxK] * B^T (B stored [N][K] hi/lo bf16) + bias
// EPI: 0 = fp32 C; 1 = GELU -> split bf16; 2 = fp32 residual add in-place; 3 = split bf16 (no act)
template<int EPI>
__device__ __forceinline__ void gemm_body(
    const bf16* __restrict__ Ahi, const bf16* __restrict__ Alo,
    const bf16* __restrict__ Bhi, const bf16* __restrict__ Blo,
    const float* __restrict__ bias,
    float* __restrict__ C, bf16* __restrict__ Chi, bf16* __restrict__ Clo,
    int K, int N, int Nout)
{
    extern __shared__ bf16 sm[];   // [2 buf][4 arr][128][40]
    uint32_t smb = s2u(sm);
    int tid = threadIdx.x;
    int bm = blockIdx.y * 128;
    int bn = blockIdx.x * 128;
    int warp = tid >> 5, lane = tid & 31;
    int wm = warp >> 2, wn = warp & 3;

    float acc[4][4][4];
    #pragma unroll
    for (int i = 0; i < 4; i++)
        #pragma unroll
        for (int j = 0; j < 4; j++)
            #pragma unroll
            for (int k = 0; k < 4; k++) acc[i][j][k] = 0.f;

    const bf16* srcs[4] = { Ahi + (long)bm * K, Alo + (long)bm * K,
                            Bhi + (long)bn * K, Blo + (long)bn * K };

    auto issue = [&](int b, int kt) {
        int k0 = kt * 32;
        #pragma unroll
        for (int arr = 0; arr < 4; arr++) {
            #pragma unroll
            for (int i = 0; i < 2; i++) {
                int ch = tid + i * 256;
                int row = ch >> 2, cg = ch & 3;
                uint32_t dst = smb + ((((b * 4 + arr) * 128 + row) * 40) + cg * 8) * 2;
                cp16(dst, srcs[arr] + (long)row * K + k0 + cg * 8);
            }
        }
    };

    int nk = K >> 5;
    issue(0, 0); CP_COMMIT;

    for (int kt = 0; kt < nk; ++kt) {
        int cur = kt & 1;
        if (kt + 1 < nk) { issue(cur ^ 1, kt + 1); CP_COMMIT; CP_WAIT1; }
        else            { CP_WAIT0; }
        __syncthreads();

        #pragma unroll
        for (int ks = 0; ks < 2; ++ks) {
            int lrow = lane & 15, lcg = lane >> 4;
            uint32_t ah[4][4], al[4][4];
            #pragma unroll
            for (int mf = 0; mf < 4; mf++) {
                int row = wm * 64 + mf * 16 + lrow;
                int col = ks * 16 + lcg * 8;
                uint32_t a0 = smb + ((((cur * 4 + 0) * 128 + row) * 40) + col) * 2;
                uint32_t a1 = smb + ((((cur * 4 + 1) * 128 + row) * 40) + col) * 2;
                ldsm4(ah[mf][0], ah[mf][1], ah[mf][2], ah[mf][3], a0);
                ldsm4(al[mf][0], al[mf][1], al[mf][2], al[mf][3], a1);
            }
            uint32_t bh[2][4], bl[2][4];
            #pragma unroll
            for (int nf2 = 0; nf2 < 2; nf2++) {
                int row = wn * 32 + nf2 * 16 + lrow;
                int col = ks * 16 + lcg * 8;
                uint32_t b0 = smb + ((((cur * 4 + 2) * 128 + row) * 40) + col) * 2;
                uint32_t b1 = smb + ((((cur * 4 + 3) * 128 + row) * 40) + col) * 2;
                ldsm4(bh[nf2][0], bh[nf2][1], bh[nf2][2], bh[nf2][3], b0);
                ldsm4(bl[nf2][0], bl[nf2][1], bl[nf2][2], bl[nf2][3], b1);
            }
            #pragma unroll
            for (int mf = 0; mf < 4; mf++) {
                #pragma unroll
                for (int nf = 0; nf < 4; nf++) {
                    int g = nf >> 1, o = nf & 1;
                    uint32_t b0h = bh[g][o], b1h = bh[g][o + 2];
                    uint32_t b0l = bl[g][o], b1l = bl[g][o + 2];
                    float* c = acc[mf][nf];
                    mma_bf16(c, ah[mf][0], ah[mf][1], ah[mf][2], ah[mf][3], b0h, b1h);
                    mma_bf16(c, ah[mf][0], ah[mf][1], ah[mf][2], ah[mf][3], b0l, b1l);
                    mma_bf16(c, al[mf][0], al[mf][1], al[mf][2], al[mf][3], b0h, b1h);
                }
            }
        }
        __syncthreads();
    }

    int r = lane >> 2, c2 = (lane & 3) * 2;
    #pragma unroll
    for (int mf = 0; mf < 4; mf++) {
        #pragma unroll
        for (int nf = 0; nf < 4; nf++) {
            #pragma unroll
            for (int half = 0; half < 2; half++) {
                long row = bm + wm * 64 + mf * 16 + r + half * 8;
                #pragma unroll
                for (int e = 0; e < 2; e++) {
                    int col = bn + wn * 32 + nf * 8 + c2 + e;
                    if (col < Nout) {
                        float v = acc[mf][nf][half * 2 + e] + bias[col];
                        if (EPI == 1 || EPI == 3) {
                            if (EPI == 1)
                                v = 0.5f * v * (1.f + erff(v * 0.70710678118654752f));
                            bf16 h, l; split2(v, h, l);
                            Chi[row * N + col] = h;
                            Clo[row * N + col] = l;
                        } else if (EPI == 2) {
                            v += C[row * (long)Nout + col];
                            C[row * (long)Nout + col] = v;
                        } else {
                            C[row * (long)Nout + col] = v;
                        }
                    }
                }
            }
        }
    }
}

template<int EPI>
__global__ __launch_bounds__(256, 1) void gemm_kernel(
    const bf16* __restrict__ Ahi, const bf16* __restrict__ Alo,
    const bf16* __restrict__ Bhi, const bf16* __restrict__ Blo,
    const float* __restrict__ bias,
    float* __restrict__ C, bf16* __restrict__ Chi, bf16* __restrict__ Clo,
    int K, int N, int Nout)
{
    gemm_body<EPI>(Ahi, Alo, Bhi, Blo, bias, C, Chi, Clo, K, N, Nout);
}

// fused QKV: EPI=3 split-bf16 outputs, blockIdx.z selects q/k/v
__global__ __launch_bounds__(256, 1) void gemm_qkv_kernel(
    const bf16* __restrict__ Ahi, const bf16* __restrict__ Alo,
    const bf16* __restrict__ whi, const bf16* __restrict__ wlo,
    const float* __restrict__ bq, const float* __restrict__ bk, const float* __restrict__ bv,
    bf16* __restrict__ qhi, bf16* __restrict__ qlo,
    bf16* __restrict__ khi, bf16* __restrict__ klo,
    bf16* __restrict__ vhi, bf16* __restrict__ vlo)
{
    int z = blockIdx.z;
    const bf16* Bh = whi + (size_t)z * WSQ;
    const bf16* Bl = wlo + (size_t)z * WSQ;
    const float* bias = (z == 0) ? bq : (z == 1) ? bk : bv;
    bf16* Chi = (z == 0) ? qhi : (z == 1) ? khi : vhi;
    bf16* Clo = (z == 0) ? qlo : (z == 1) ? klo : vlo;
    gemm_body<3>(Ahi, Alo, Bh, Bl, bias, nullptr, Chi, Clo, Dq_, Dq_, Dq_);
}

// ---------------- HMMA flash attention ----------------
// block: 128 threads (4 warps), 64 q-rows; warp w owns q rows [w*16, w*16+16)
// smem tiles (bf16, row stride 72): Qh Ql Kh Kl Vh Vl, each [64][72]
#define AT_STRIDE 72
#define AT_TILE (64 * AT_STRIDE)           // halves
#define ATTN_SMEM (6 * AT_TILE * 2)        // 55296 bytes

__global__ __launch_bounds__(128, 4) void attn_kernel(
    const bf16* __restrict__ Qh_g, const bf16* __restrict__ Ql_g,
    const bf16* __restrict__ Kh_g, const bf16* __restrict__ Kl_g,
    const bf16* __restrict__ Vh_g, const bf16* __restrict__ Vl_g,
    bf16* __restrict__ Ohi, bf16* __restrict__ Olo)
{
    extern __shared__ bf16 asm_[];
    uint32_t smb = s2u(asm_);
    uint32_t sQh = smb;
    uint32_t sQl = sQh + AT_TILE * 2;
    uint32_t sKh = sQl + AT_TILE * 2;
    uint32_t sKl = sKh + AT_TILE * 2;
    uint32_t sVh = sKl + AT_TILE * 2;
    uint32_t sVl = sVh + AT_TILE * 2;

    int t = threadIdx.x, warp = t >> 5, lane = t & 31;
    int q0 = blockIdx.x * 64, h = blockIdx.y, b = blockIdx.z;

    long rowbase = (long)(b * Sq_ + q0) * Dq_ + h * DHq_;

    // load Q tile (hi/lo): 512 chunks of 16B per array, 4 per thread
    #pragma unroll
    for (int i = 0; i < 4; i++) {
        int idx = t + i * 128;
        int row = idx >> 3, ch = idx & 7;
        uint32_t doff = (uint32_t)(row * AT_STRIDE + ch * 8) * 2;
        cp16(sQh + doff, Qh_g + rowbase + (long)row * Dq_ + ch * 8);
        cp16(sQl + doff, Ql_g + rowbase + (long)row * Dq_ + ch * 8);
    }

    float m[2] = { -1e30f, -1e30f }, l[2] = { 0.f, 0.f };
    float oacc[8][4];
    #pragma unroll
    for (int i = 0; i < 8; i++)
        #pragma unroll
        for (int j = 0; j < 4; j++) oacc[i][j] = 0.f;

    int lrow = lane & 15, lcg = lane >> 4;

    for (int j0 = 0; j0 <= q0; j0 += 64) {
        long kbase = (long)(b * Sq_ + j0) * Dq_ + h * DHq_;
        #pragma unroll
        for (int i = 0; i < 4; i++) {
            int idx = t + i * 128;
            int row = idx >> 3, ch = idx & 7;
            uint32_t doff = (uint32_t)(row * AT_STRIDE + ch * 8) * 2;
            long goff = kbase + (long)row * Dq_ + ch * 8;
            cp16(sKh + doff, Kh_g + goff);
            cp16(sKl + doff, Kl_g + goff);
            cp16(sVh + doff, Vh_g + goff);
            cp16(sVl + doff, Vl_g + goff);
        }
        CP_COMMIT; CP_WAIT0;
        __syncthreads();

        // ---- scores: sacc[nf][4], nf = key n8-group (8 groups = 64 keys) ----
        float sacc[8][4];
        #pragma unroll
        for (int i = 0; i < 8; i++)
            #pragma unroll
            for (int j = 0; j < 4; j++) sacc[i][j] = 0.f;

        #pragma unroll
        for (int ks = 0; ks < 4; ++ks) {
            int acol = ks * 16 + lcg * 8;
            uint32_t qh[4], ql[4];
            uint32_t qaddr = (uint32_t)((warp * 16 + lrow) * AT_STRIDE + acol) * 2;
            ldsm4(qh[0], qh[1], qh[2], qh[3], sQh + qaddr);
            ldsm4(ql[0], ql[1], ql[2], ql[3], sQl + qaddr);
            #pragma unroll
            for (int kg = 0; kg < 4; ++kg) {
                uint32_t kh[4], kl[4];
                uint32_t kaddr = (uint32_t)((kg * 16 + lrow) * AT_STRIDE + acol) * 2;
                ldsm4(kh[0], kh[1], kh[2], kh[3], sKh + kaddr);
                ldsm4(kl[0], kl[1], kl[2], kl[3], sKl + kaddr);
                #pragma unroll
                for (int o = 0; o < 2; ++o) {
                    float* c = sacc[kg * 2 + o];
                    mma_bf16(c, qh[0], qh[1], qh[2], qh[3], kh[o], kh[o + 2]);
                    mma_bf16(c, qh[0], qh[1], qh[2], qh[3], kl[o], kl[o + 2]);
                    mma_bf16(c, ql[0], ql[1], ql[2], ql[3], kh[o], kh[o + 2]);
                }
            }
        }

        // ---- softmax (online) ----
        int r0loc = warp * 16 + (lane >> 2);
        bool diag = (j0 == q0);
        float mx[2] = { -1e30f, -1e30f };
        #pragma unroll
        for (int nf = 0; nf < 8; nf++) {
            #pragma unroll
            for (int i = 0; i < 4; i++) {
                float v = sacc[nf][i] * 0.125f;
                if (diag) {
                    int col = nf * 8 + (lane & 3) * 2 + (i & 1);
                    int row = r0loc + ((i >> 1) ? 8 : 0);
                    if (col > row) v = -1e30f;
                }
                sacc[nf][i] = v;
                mx[i >> 1] = fmaxf(mx[i >> 1], v);
            }
        }
        #pragma unroll
        for (int o = 1; o < 4; o <<= 1) {
            mx[0] = fmaxf(mx[0], __shfl_xor_sync(0xffffffffu, mx[0], o));
            mx[1] = fmaxf(mx[1], __shfl_xor_sync(0xffffffffu, mx[1], o));
        }
        float fac[2], sum[2] = { 0.f, 0.f };
        #pragma unroll
        for (int j = 0; j < 2; j++) {
            float mnew = fmaxf(m[j], mx[j]);
            fac[j] = __expf(m[j] - mnew);
            m[j] = mnew;
        }
        #pragma unroll
        for (int nf = 0; nf < 8; nf++) {
            #pragma unroll
            for (int i = 0; i < 4; i++) {
                float p = __expf(sacc[nf][i] - m[i >> 1]);
                sacc[nf][i] = p;
                sum[i >> 1] += p;
            }
        }
        #pragma unroll
        for (int o = 1; o < 4; o <<= 1) {
            sum[0] += __shfl_xor_sync(0xffffffffu, sum[0], o);
            sum[1] += __shfl_xor_sync(0xffffffffu, sum[1], o);
        }
        #pragma unroll
        for (int j = 0; j < 2; j++) l[j] = l[j] * fac[j] + sum[j];
        #pragma unroll
        for (int nf = 0; nf < 8; nf++) {
            oacc[nf][0] *= fac[0]; oacc[nf][1] *= fac[0];
            oacc[nf][2] *= fac[1]; oacc[nf][3] *= fac[1];
        }

        // ---- PV: O += P * V ----
        #pragma unroll
        for (int t2 = 0; t2 < 4; ++t2) {
            // pack P fragments (A operand) hi/lo from sacc[2*t2], sacc[2*t2+1]
            float* p0 = sacc[2 * t2];
            float* p1 = sacc[2 * t2 + 1];
            bf16 h00, h01, h02, h03, h10, h11, h12, h13;
            h00 = __float2bfloat16(p0[0]); h01 = __float2bfloat16(p0[1]);
            h02 = __float2bfloat16(p0[2]); h03 = __float2bfloat16(p0[3]);
            h10 = __float2bfloat16(p1[0]); h11 = __float2bfloat16(p1[1]);
            h12 = __float2bfloat16(p1[2]); h13 = __float2bfloat16(p1[3]);
            uint32_t pah[4], pal[4];
            pah[0] = packbf2(__bfloat162float(h00), __bfloat162float(h01));
            pah[1] = packbf2(__bfloat162float(h02), __bfloat162float(h03));
            pah[2] = packbf2(__bfloat162float(h10), __bfloat162float(h11));
            pah[3] = packbf2(__bfloat162float(h12), __bfloat162float(h13));
            pal[0] = packbf2(p0[0] - __bfloat162float(h00), p0[1] - __bfloat162float(h01));
            pal[1] = packbf2(p0[2] - __bfloat162float(h02), p0[3] - __bfloat162float(h03));
            pal[2] = packbf2(p1[0] - __bfloat162float(h10), p1[1] - __bfloat162float(h11));
            pal[3] = packbf2(p1[2] - __bfloat162float(h12), p1[3] - __bfloat162float(h13));

            #pragma unroll
            for (int nd = 0; nd < 4; ++nd) {
                // ldmatrix.trans on V[key][dim] -> B frags of V^T
                uint32_t vrow = (uint32_t)(t2 * 16 + ((lane >> 4) << 3) + (lane & 7));
                uint32_t vcol = (uint32_t)(nd * 16 + (((lane >> 3) & 1) << 3));
                uint32_t vaddr = (vrow * AT_STRIDE + vcol) * 2;
                uint32_t vh[4], vl[4];
                ldsm4t(vh[0], vh[1], vh[2], vh[3], sVh + vaddr);
                ldsm4t(vl[0], vl[1], vl[2], vl[3], sVl + vaddr);
                #pragma unroll
                for (int o = 0; o < 2; ++o) {
                    float* c = oacc[nd * 2 + o];
                    mma_bf16(c, pah[0], pah[1], pah[2], pah[3], vh[o], vh[o + 2]);
                    mma_bf16(c, pah[0], pah[1], pah[2], pah[3], vl[o], vl[o + 2]);
                    mma_bf16(c, pal[0], pal[1], pal[2], pal[3], vh[o], vh[o + 2]);
                }
            }
        }
        __syncthreads();
    }

    // ---- epilogue: O/l -> bf16 hi/lo split ----
    float inv0 = 1.f / l[0], inv1 = 1.f / l[1];
    long row0 = (long)(b * Sq_ + q0 + warp * 16 + (lane >> 2));
    long row1 = row0 + 8;
    #pragma unroll
    for (int nf = 0; nf < 8; nf++) {
        int col = h * DHq_ + nf * 8 + (lane & 3) * 2;
        float v0 = oacc[nf][0] * inv0, v1 = oacc[nf][1] * inv0;
        float v2 = oacc[nf][2] * inv1, v3 = oacc[nf][3] * inv1;
        bf16 h0, l0, h1, l1, h2, l2, h3, l3;
        split2(v0, h0, l0); split2(v1, h1, l1);
        split2(v2, h2, l2); split2(v3, h3, l3);
        *(__nv_bfloat162*)&Ohi[row0 * Dq_ + col] = __nv_bfloat162(h0, h1);
        *(__nv_bfloat162*)&Olo[row0 * Dq_ + col] = __nv_bfloat162(l0, l1);
        *(__nv_bfloat162*)&Ohi[row1 * Dq_ + col] = __nv_bfloat162(h2, h3);
        *(__nv_bfloat162*)&Olo[row1 * Dq_ + col] = __nv_bfloat162(l2, l3);
    }
}

// ---------------- launcher ----------------
extern "C" void kernel_launch(void* const* d_in, const int* in_sizes, int n_in,
                              void* d_out, int out_size) {
    const int*   x    = (const int*)  d_in[0];
    const float* tok  = (const float*)d_in[1];
    const float* pos  = (const float*)d_in[2];
    const float* Wq   = (const float*)d_in[3];
    const float* bq   = (const float*)d_in[4];
    const float* Wk   = (const float*)d_in[5];
    const float* bk   = (const float*)d_in[6];
    const float* Wv   = (const float*)d_in[7];
    const float* bv   = (const float*)d_in[8];
    const float* Wo   = (const float*)d_in[9];
    const float* bo   = (const float*)d_in[10];
    const float* ln1w = (const float*)d_in[11];
    const float* ln1b = (const float*)d_in[12];
    const float* ln2w = (const float*)d_in[13];
    const float* ln2b = (const float*)d_in[14];
    const float* W1   = (const float*)d_in[15];
    const float* b1   = (const float*)d_in[16];
    const float* W2   = (const float*)d_in[17];
    const float* b2   = (const float*)d_in[18];
    const float* lnfw = (const float*)d_in[19];
    const float* lnfb = (const float*)d_in[20];
    const float* Wout = (const float*)d_in[21];
    const float* bout = (const float*)d_in[22];
    float* out = (float*)d_out;

    float *h;
    bf16 *ahi, *alo, *qhi, *qlo, *khi, *klo, *vhi, *vlo, *ohi, *olo, *fhi, *flo, *whi, *wlo;
    cudaGetSymbolAddress((void**)&h, g_h);
    cudaGetSymbolAddress((void**)&ahi, g_ahi);
    cudaGetSymbolAddress((void**)&alo, g_alo);
    cudaGetSymbolAddress((void**)&qhi, g_qhi);
    cudaGetSymbolAddress((void**)&qlo, g_qlo);
    cudaGetSymbolAddress((void**)&khi, g_khi);
    cudaGetSymbolAddress((void**)&klo, g_klo);
    cudaGetSymbolAddress((void**)&vhi, g_vhi);
    cudaGetSymbolAddress((void**)&vlo, g_vlo);
    cudaGetSymbolAddress((void**)&ohi, g_ohi);
    cudaGetSymbolAddress((void**)&olo, g_olo);
    cudaGetSymbolAddress((void**)&fhi, g_fhi);
    cudaGetSymbolAddress((void**)&flo, g_flo);
    cudaGetSymbolAddress((void**)&whi, g_whi);
    cudaGetSymbolAddress((void**)&wlo, g_wlo);

    const int GEMM_SMEM = 2 * 4 * 128 * 40 * 2;       // 81920
    cudaFuncSetAttribute(gemm_kernel<0>, cudaFuncAttributeMaxDynamicSharedMemorySize, GEMM_SMEM);
    cudaFuncSetAttribute(gemm_kernel<1>, cudaFuncAttributeMaxDynamicSharedMemorySize, GEMM_SMEM);
    cudaFuncSetAttribute(gemm_kernel<2>, cudaFuncAttributeMaxDynamicSharedMemorySize, GEMM_SMEM);
    cudaFuncSetAttribute(gemm_qkv_kernel, cudaFuncAttributeMaxDynamicSharedMemorySize, GEMM_SMEM);
    cudaFuncSetAttribute(attn_kernel, cudaFuncAttributeMaxDynamicSharedMemorySize, ATTN_SMEM);

    // ---- weight prep (batched) ----
    dim3 tb(32, 8);
    tsplit_sq_kernel<<<dim3(24, 24, 48), tb>>>(Wq, Wk, Wv, Wo, whi, wlo);
    tsplit_w1_kernel<<<dim3(Hq_ / 32, 24, 12), tb>>>(W1, whi, wlo);
    tsplit_w2_kernel<<<dim3(24, Hq_ / 32, 12), tb>>>(W2, whi, wlo);
    tsplit_out_kernel<<<dim3(VPAD_ / 32, 24), tb>>>(Wout, whi, wlo);

    embed_kernel<<<Mq_, 256>>>(x, tok, pos, h);

    dim3 gD(Dq_ / 128, Mq_ / 128);
    dim3 gH(Hq_ / 128, Mq_ / 128);
    dim3 gV(VPAD_ / 128, Mq_ / 128);
    dim3 gQKV(Dq_ / 128, Mq_ / 128, 3);
    dim3 gAtt(Sq_ / 64, NHq_, Bq_);

    for (int i = 0; i < Lq_; ++i) {
        size_t off = (size_t)i * LWBLK;
        ln_kernel<<<Mq_, 256>>>(h, ln1w + i * Dq_, ln1b + i * Dq_, ahi, alo);
        gemm_qkv_kernel<<<gQKV, 256, GEMM_SMEM>>>(ahi, alo, whi + off, wlo + off,
            bq + i * Dq_, bk + i * Dq_, bv + i * Dq_,
            qhi, qlo, khi, klo, vhi, vlo);
        attn_kernel<<<gAtt, 128, ATTN_SMEM>>>(qhi, qlo, khi, klo, vhi, vlo, ohi, olo);
        gemm_kernel<2><<<gD, 256, GEMM_SMEM>>>(ohi, olo, whi + off + 3 * WSQ, wlo + off + 3 * WSQ,
            bo + i * Dq_, h, nullptr, nullptr, Dq_, Dq_, Dq_);
        ln_kernel<<<Mq_, 256>>>(h, ln2w + i * Dq_, ln2b + i * Dq_, ahi, alo);
        gemm_kernel<1><<<gH, 256, GEMM_SMEM>>>(ahi, alo, whi + off + 4 * WSQ, wlo + off + 4 * WSQ,
            b1 + i * Hq_, nullptr, fhi, flo, Dq_, Hq_, Hq_);
        gemm_kernel<2><<<gD, 256, GEMM_SMEM>>>(fhi, flo, whi + off + 4 * WSQ + WSH, wlo + off + 4 * WSQ + WSH,
            b2 + i * Dq_, h, nullptr, nullptr, Hq_, Dq_, Dq_);
    }

    ln_kernel<<<Mq_, 256>>>(h, lnfw, lnfb, ahi, alo);
    gemm_kernel<0><<<gV, 256, GEMM_SMEM>>>(ahi, alo, whi + WOUT_OFF, wlo + WOUT_OFF,
        bout, out, nullptr, nullptr, Dq_, VPAD_, Vq_);
}